// round 16
// baseline (speedup 1.0000x reference)
#include <cuda_runtime.h>
#include <cuda_fp16.h>

// Problem constants
#define Bc   16
#define Nn   10000
#define Ee   160000
#define C1   32
#define C2   16
#define C3   32
#define WPB  8
#define DMAX 64          // padded CSR slots per node (P(deg>63) ~ 1e-18 for Poisson(16))

// ---------------- scratch (device globals; zero-initialized at load) ----------
__device__ int    g_cur1[Nn];
__device__ int    g_cur2[Nn];
__device__ int2   g_meta1[(size_t)Nn * DMAX + 4];   // +4 pad: prefetch overrun safety
__device__ int2   g_meta2[(size_t)Nn * DMAX + 4];
__device__ float  g_gi1[Bc * Nn];               // [n][b] fp32
__device__ float  g_gi2[Bc * Nn];
__device__ __half g_gj1h[Bc * Nn];              // [n][b] fp16 (per-edge gather)
__device__ __half g_gj2h[Bc * Nn];
// fp16 feature arrays, batch-minor [n][b][c]
__device__ uint4  g_x16[(size_t)Nn * Bc * C1 / 8];   // 64 uint4 per node
__device__ uint4  g_h16[(size_t)Nn * Bc * C2 / 8];   // 32 uint4 per node

// fused: blocks [0,FB) scatter edges (1 edge/thread, both graphs);
//        blocks [FB,FB+PB) warp-cooperative gate + X->fp16 transpose
#define FB  625   // Ee / 256
#define PB  625   // 5000 warps * 32 rows = 160000 rows
__global__ void k_fill_prep(const int* __restrict__ ei1, const float* __restrict__ ew1,
                            const int* __restrict__ ei2, const float* __restrict__ ew2,
                            const float* __restrict__ X, const float* __restrict__ gw) {
    if (blockIdx.x < FB) {
        int e = blockIdx.x * 256 + threadIdx.x;
        int d1 = ei1[Ee + e], s1 = ei1[e];
        int d2 = ei2[Ee + e], s2 = ei2[e];
        float w1v = ew1[e], w2v = ew2[e];
        int p1 = atomicAdd(&g_cur1[d1], 1);
        int p2 = atomicAdd(&g_cur2[d2], 1);
        if (p1 < DMAX) g_meta1[d1 * DMAX + p1] = make_int2(s1, __float_as_int(w1v));
        if (p2 < DMAX) g_meta2[d2 * DMAX + p2] = make_int2(s2, __float_as_int(w2v));
    } else {
        int wid  = (blockIdx.x - FB) * 8 + (threadIdx.x >> 5);   // 0..4999
        int lane = threadIdx.x & 31;
        int rgrp = lane >> 3;      // 0..3 : row within 4-row step
        int ch   = lane & 7;       // 0..7 : float4 chunk within row
        float4 wi = __ldg((const float4*)(gw + ch * 4));
        float4 wj = __ldg((const float4*)(gw + C1 + ch * 4));
        uint2* xt = (uint2*)g_x16;
#pragma unroll
        for (int s = 0; s < 8; s++) {
            int r = wid * 32 + s * 4 + rgrp;        // row = n*16 + b
            int n = r >> 4, b = r & 15;
            float4 v = *(const float4*)(X + ((size_t)b * Nn + n) * C1 + ch * 4);
            float vi = v.x * wi.x; vi = fmaf(v.y, wi.y, vi);
            vi = fmaf(v.z, wi.z, vi); vi = fmaf(v.w, wi.w, vi);
            float vj = v.x * wj.x; vj = fmaf(v.y, wj.y, vj);
            vj = fmaf(v.z, wj.z, vj); vj = fmaf(v.w, wj.w, vj);
#pragma unroll
            for (int off = 1; off < 8; off <<= 1) {
                vi += __shfl_xor_sync(0xffffffffu, vi, off);
                vj += __shfl_xor_sync(0xffffffffu, vj, off);
            }
            __half2 ha = __float22half2_rn(make_float2(v.x, v.y));
            __half2 hb = __float22half2_rn(make_float2(v.z, v.w));
            uint2 u;
            u.x = *(unsigned*)&ha; u.y = *(unsigned*)&hb;
            xt[r * 8 + ch] = u;
            if (ch == 0) {
                g_gi1[r]  = vi;
                g_gj1h[r] = __float2half_rn(vj);
            }
        }
    }
}

// ---------------- layer 1 fused: edge aggregation + combine ------------------
__global__ void __launch_bounds__(WPB * 32, 5)
k_l1(const float* __restrict__ gw, const float* __restrict__ gb,
     const float* __restrict__ ampw, const float* __restrict__ w,
     const float* __restrict__ bias, const float* __restrict__ gw2) {
    __shared__ float smbuf[WPB][16][2 * C1];   // [b][x(32)|aggr(32)]
    int n = blockIdx.x * WPB + (threadIdx.x >> 5);
    if (n >= Nn) return;
    int lane = threadIdx.x & 31;
    int bq = lane >> 2;          // 0..7
    int cq = lane & 3;           // 0..3
    float (*sm)[2 * C1] = smbuf[threadIdx.x >> 5];

    float wge = __ldg(&gw[2 * C1]);
    float gbv = __ldg(gb);
    float givb = ((lane < 16) ? g_gi1[n * 16 + lane] : 0.f) + gbv;

    int cnt = g_cur1[n];
    if (lane == 0) g_cur1[n] = 0;        // reset for next replay (graph-safe)
    if (cnt > DMAX) cnt = DMAX;
    int beg = n * DMAX;
    int end = beg + cnt;

    const int off0 = bq * 4 + cq;
    const int off1 = 32 + bq * 4 + cq;

    float acc[16];
#pragma unroll
    for (int i = 0; i < 16; i++) acc[i] = 0.f;

    if (beg < end) {
        int2 mc = g_meta1[beg];
        int2 mn = (beg + 1 < end) ? g_meta1[beg + 1] : mc;
        float gjc = (lane < 16) ? __half2float(g_gj1h[mc.x * 16 + lane]) : 0.f;
        uint4 x0c = g_x16[(size_t)mc.x * 64 + off0];
        uint4 x1c = g_x16[(size_t)mc.x * 64 + off1];

#pragma unroll 2
        for (int k = beg; k < end; k++) {
            int2  mnn = (k + 2 < end) ? g_meta1[k + 2] : mn;
            float gjn = (lane < 16) ? __half2float(g_gj1h[mn.x * 16 + lane]) : 0.f;
            uint4 x0n = g_x16[(size_t)mn.x * 64 + off0];
            uint4 x1n = g_x16[(size_t)mn.x * 64 + off1];

            float ew = __int_as_float(mc.y);
            float z  = givb + gjc + ew * wge;
            float lamb = __fdividef(ew, 1.f + __expf(-z));   // lane = batch (lanes<16)
            float c0 = __shfl_sync(0xffffffffu, lamb, bq);
            float c1 = __shfl_sync(0xffffffffu, lamb, 8 + bq);

            const __half2* hp0 = (const __half2*)&x0c;
            const __half2* hp1 = (const __half2*)&x1c;
#pragma unroll
            for (int j = 0; j < 4; j++) {
                float2 f0 = __half22float2(hp0[j]);
                float2 f1 = __half22float2(hp1[j]);
                acc[2*j]     = fmaf(c0, f0.x, acc[2*j]);
                acc[2*j+1]   = fmaf(c0, f0.y, acc[2*j+1]);
                acc[8+2*j]   = fmaf(c1, f1.x, acc[8+2*j]);
                acc[8+2*j+1] = fmaf(c1, f1.y, acc[8+2*j+1]);
            }
            mc = mn; mn = mnn; gjc = gjn; x0c = x0n; x1c = x1n;
        }
    }

    float cntf = (float)cnt;
    if (cntf < 1.f) cntf = 1.f;
    float inv = __fdividef(1.f, cntf);
    float4 av0 = *(const float4*)(ampw + 8 * cq);
    float4 av1 = *(const float4*)(ampw + 8 * cq + 4);
    av0.x *= inv; av0.y *= inv; av0.z *= inv; av0.w *= inv;
    av1.x *= inv; av1.y *= inv; av1.z *= inv; av1.w *= inv;

    // stage aggr into smem [b][32 + c]
    *(float4*)&sm[bq][C1 + 8 * cq] =
        make_float4(acc[0]*av0.x, acc[1]*av0.y, acc[2]*av0.z, acc[3]*av0.w);
    *(float4*)&sm[bq][C1 + 8 * cq + 4] =
        make_float4(acc[4]*av1.x, acc[5]*av1.y, acc[6]*av1.z, acc[7]*av1.w);
    *(float4*)&sm[8 + bq][C1 + 8 * cq] =
        make_float4(acc[8]*av0.x, acc[9]*av0.y, acc[10]*av0.z, acc[11]*av0.w);
    *(float4*)&sm[8 + bq][C1 + 8 * cq + 4] =
        make_float4(acc[12]*av1.x, acc[13]*av1.y, acc[14]*av1.z, acc[15]*av1.w);

    // stage x_dst rows from g_x16 (fp16, contiguous, L2-hot)
#pragma unroll
    for (int hf = 0; hf < 2; hf++) {
        uint4 u = g_x16[(size_t)n * 64 + hf * 32 + lane];
        int b = (lane >> 2) + 8 * hf;
        int cg = lane & 3;
        const __half2* hp = (const __half2*)&u;
#pragma unroll
        for (int j = 0; j < 4; j++) {
            float2 f = __half22float2(hp[j]);
            sm[b][cg * 8 + 2*j]     = f.x;
            sm[b][cg * 8 + 2*j + 1] = f.y;
        }
    }
    __syncwarp();

    // combine: per batch, split-K (oc = lane&15, kh = lane>>4)
    int oc = lane & 15;
    int kh = lane >> 4;
    float wv[32];
#pragma unroll
    for (int kk = 0; kk < 32; kk++)
        wv[kk] = __ldg(&w[(kh * 32 + kk) * C2 + oc]);
    float bv   = __ldg(&bias[oc]);
    float gsel = __ldg(&gw2[lane]);     // lanes 0-15: wg_i[oc]; lanes 16-31: wg_j[oc]

    __half* hout = (__half*)g_h16;
#pragma unroll 4
    for (int b = 0; b < 16; b++) {
        float p0 = 0.f, p1 = 0.f;
#pragma unroll
        for (int kq = 0; kq < 8; kq += 2) {
            float4 m0 = *(float4*)&sm[b][kh * 32 + kq * 4];
            float4 m1 = *(float4*)&sm[b][kh * 32 + kq * 4 + 4];
            p0 = fmaf(m0.x, wv[kq*4+0], p0);
            p0 = fmaf(m0.y, wv[kq*4+1], p0);
            p0 = fmaf(m0.z, wv[kq*4+2], p0);
            p0 = fmaf(m0.w, wv[kq*4+3], p0);
            p1 = fmaf(m1.x, wv[kq*4+4], p1);
            p1 = fmaf(m1.y, wv[kq*4+5], p1);
            p1 = fmaf(m1.z, wv[kq*4+6], p1);
            p1 = fmaf(m1.w, wv[kq*4+7], p1);
        }
        float p = p0 + p1;
        p += __shfl_xor_sync(0xffffffffu, p, 16);
        float o = p + bv;
        o = (o > 0.f) ? o : 0.01f * o;

        // gate dots: lanes 0-15 reduce vi, lanes 16-31 reduce vj (same o per oc)
        float v = o * gsel;
#pragma unroll
        for (int off = 1; off < 16; off <<= 1)
            v += __shfl_xor_sync(0xffffffffu, v, off);

        if (lane < 16)
            hout[((size_t)n * 16 + b) * C2 + oc] = __float2half_rn(o);
        if (lane == 0)  g_gi2[n * 16 + b]  = v;
        if (lane == 16) g_gj2h[n * 16 + b] = __float2half_rn(v);
    }
}

// ---------------- layer 2 fused: edge aggregation + combine ------------------
__global__ void __launch_bounds__(WPB * 32, 5)
k_l2(const float* __restrict__ gw, const float* __restrict__ gb,
     const float* __restrict__ ampw, const float* __restrict__ w,
     const float* __restrict__ bias, float* __restrict__ outp) {
    __shared__ float smbuf[WPB][16][2 * C2];   // [b][h(16)|aggr(16)]
    int n = blockIdx.x * WPB + (threadIdx.x >> 5);
    if (n >= Nn) return;
    int lane = threadIdx.x & 31;
    int bl = lane >> 1;          // 0..15
    int ch = lane & 1;           // 0..1
    float (*sm)[2 * C2] = smbuf[threadIdx.x >> 5];

    float wge = __ldg(&gw[2 * C2]);
    float gbv = __ldg(gb);
    float givb = ((lane < 16) ? g_gi2[n * 16 + lane] : 0.f) + gbv;

    int cnt = g_cur2[n];
    if (lane == 0) g_cur2[n] = 0;        // reset for next replay (graph-safe)
    if (cnt > DMAX) cnt = DMAX;
    int beg = n * DMAX;
    int end = beg + cnt;

    float acc[8];
#pragma unroll
    for (int i = 0; i < 8; i++) acc[i] = 0.f;

    if (beg < end) {
        int2 mc = g_meta2[beg];
        int2 mn = (beg + 1 < end) ? g_meta2[beg + 1] : mc;
        float gjc = (lane < 16) ? __half2float(g_gj2h[mc.x * 16 + lane]) : 0.f;
        uint4 xc = g_h16[(size_t)mc.x * 32 + lane];

#pragma unroll 2
        for (int k = beg; k < end; k++) {
            int2  mnn = (k + 2 < end) ? g_meta2[k + 2] : mn;
            float gjn = (lane < 16) ? __half2float(g_gj2h[mn.x * 16 + lane]) : 0.f;
            uint4 xn = g_h16[(size_t)mn.x * 32 + lane];

            float ew = __int_as_float(mc.y);
            float z  = givb + gjc + ew * wge;
            float lamb = __fdividef(ew, 1.f + __expf(-z));
            float c0 = __shfl_sync(0xffffffffu, lamb, bl);

            const __half2* hp = (const __half2*)&xc;
#pragma unroll
            for (int j = 0; j < 4; j++) {
                float2 f = __half22float2(hp[j]);
                acc[2*j]   = fmaf(c0, f.x, acc[2*j]);
                acc[2*j+1] = fmaf(c0, f.y, acc[2*j+1]);
            }
            mc = mn; mn = mnn; gjc = gjn; xc = xn;
        }
    }

    float cntf = (float)cnt;
    if (cntf < 1.f) cntf = 1.f;
    float inv = __fdividef(1.f, cntf);
    float4 av0 = *(const float4*)(ampw + 8 * ch);
    float4 av1 = *(const float4*)(ampw + 8 * ch + 4);
    av0.x *= inv; av0.y *= inv; av0.z *= inv; av0.w *= inv;
    av1.x *= inv; av1.y *= inv; av1.z *= inv; av1.w *= inv;

    // stage aggr into smem [b][16 + c]
    *(float4*)&sm[bl][C2 + 8 * ch] =
        make_float4(acc[0]*av0.x, acc[1]*av0.y, acc[2]*av0.z, acc[3]*av0.w);
    *(float4*)&sm[bl][C2 + 8 * ch + 4] =
        make_float4(acc[4]*av1.x, acc[5]*av1.y, acc[6]*av1.z, acc[7]*av1.w);

    // stage own h rows: one uint4 per lane (b = lane>>1, channels (lane&1)*8..)
    {
        uint4 u = g_h16[(size_t)n * 32 + lane];
        int b = lane >> 1;
        int off = (lane & 1) * 8;
        const __half2* hp = (const __half2*)&u;
#pragma unroll
        for (int j = 0; j < 4; j++) {
            float2 f = __half22float2(hp[j]);
            sm[b][off + 2*j]     = f.x;
            sm[b][off + 2*j + 1] = f.y;
        }
    }
    __syncwarp();

    // combine: per batch, oc = lane (32 outputs)
    float wv[32];
#pragma unroll
    for (int kk = 0; kk < 32; kk++)
        wv[kk] = __ldg(&w[kk * C3 + lane]);
    float bv = __ldg(&bias[lane]);

#pragma unroll 4
    for (int b = 0; b < 16; b++) {
        float p0 = bv, p1 = 0.f;
#pragma unroll
        for (int kq = 0; kq < 8; kq += 2) {
            float4 m0 = *(float4*)&sm[b][kq * 4];
            float4 m1 = *(float4*)&sm[b][kq * 4 + 4];
            p0 = fmaf(m0.x, wv[kq*4+0], p0);
            p0 = fmaf(m0.y, wv[kq*4+1], p0);
            p0 = fmaf(m0.z, wv[kq*4+2], p0);
            p0 = fmaf(m0.w, wv[kq*4+3], p0);
            p1 = fmaf(m1.x, wv[kq*4+4], p1);
            p1 = fmaf(m1.y, wv[kq*4+5], p1);
            p1 = fmaf(m1.z, wv[kq*4+6], p1);
            p1 = fmaf(m1.w, wv[kq*4+7], p1);
        }
        outp[((size_t)b * Nn + n) * C3 + lane] = p0 + p1;
    }
}

// ---------------- launch -----------------------------------------------------
extern "C" void kernel_launch(void* const* d_in, const int* in_sizes, int n_in,
                              void* d_out, int out_size) {
    const float* X       = (const float*)d_in[0];
    const int*   ei1     = (const int*)d_in[1];
    const float* ew1     = (const float*)d_in[2];
    const int*   ei2     = (const int*)d_in[4];
    const float* ew2     = (const float*)d_in[5];
    const float* amp_w1  = (const float*)d_in[7];
    const float* gate_w1 = (const float*)d_in[8];
    const float* gate_b1 = (const float*)d_in[9];
    const float* w1      = (const float*)d_in[10];
    const float* b1      = (const float*)d_in[11];
    const float* amp_w2  = (const float*)d_in[12];
    const float* gate_w2 = (const float*)d_in[13];
    const float* gate_b2 = (const float*)d_in[14];
    const float* w2      = (const float*)d_in[15];
    const float* b2      = (const float*)d_in[16];
    float* out = (float*)d_out;

    k_fill_prep<<<FB + PB, 256>>>(ei1, ew1, ei2, ew2, X, gate_w1);

    const int node_grid = (Nn + WPB - 1) / WPB;
    k_l1<<<node_grid, WPB * 32>>>(gate_w1, gate_b1, amp_w1, w1, b1, gate_w2);
    k_l2<<<node_grid, WPB * 32>>>(gate_w2, gate_b2, amp_w2, w2, b2, out);
}

// round 17
// speedup vs baseline: 1.3612x; 1.3612x over previous
#include <cuda_runtime.h>
#include <cuda_fp16.h>

// Problem constants
#define Bc   16
#define Nn   10000
#define Ee   160000
#define C1   32
#define C2   16
#define C3   32
#define WPB  8
#define DMAX 64          // padded CSR slots per node (P(deg>63) ~ 1e-18 for Poisson(16))

// ---------------- scratch (device globals; zero-initialized at load) ----------
__device__ int    g_cur1[Nn];
__device__ int    g_cur2[Nn];
__device__ int2   g_meta1[(size_t)Nn * DMAX + 4];   // +4 pad: prefetch overrun safety
__device__ int2   g_meta2[(size_t)Nn * DMAX + 4];
__device__ float  g_gi1[Bc * Nn];               // [n][b] fp32
__device__ float  g_gi2[Bc * Nn];
__device__ __half g_gj1h[Bc * Nn];              // [n][b] fp16 (per-edge gather)
__device__ __half g_gj2h[Bc * Nn];
// fp16 feature arrays, batch-minor [n][b][c]
__device__ uint4  g_x16[(size_t)Nn * Bc * C1 / 8];   // 64 uint4 per node
__device__ uint4  g_h16[(size_t)Nn * Bc * C2 / 8];   // 32 uint4 per node

// fused: blocks [0,FB) scatter edges (1 edge/thread, both graphs);
//        blocks [FB,FB+PB) warp-cooperative gate + X->fp16 transpose
#define FB  625   // Ee / 256
#define PB  625   // 5000 warps * 32 rows = 160000 rows
__global__ void k_fill_prep(const int* __restrict__ ei1, const float* __restrict__ ew1,
                            const int* __restrict__ ei2, const float* __restrict__ ew2,
                            const float* __restrict__ X, const float* __restrict__ gw) {
    if (blockIdx.x < FB) {
        int e = blockIdx.x * 256 + threadIdx.x;
        int d1 = ei1[Ee + e], s1 = ei1[e];
        int d2 = ei2[Ee + e], s2 = ei2[e];
        float w1v = ew1[e], w2v = ew2[e];
        int p1 = atomicAdd(&g_cur1[d1], 1);
        int p2 = atomicAdd(&g_cur2[d2], 1);
        if (p1 < DMAX) g_meta1[d1 * DMAX + p1] = make_int2(s1, __float_as_int(w1v));
        if (p2 < DMAX) g_meta2[d2 * DMAX + p2] = make_int2(s2, __float_as_int(w2v));
    } else {
        int wid  = (blockIdx.x - FB) * 8 + (threadIdx.x >> 5);   // 0..4999
        int lane = threadIdx.x & 31;
        int rgrp = lane >> 3;      // 0..3 : row within 4-row step
        int ch   = lane & 7;       // 0..7 : float4 chunk within row
        float4 wi = __ldg((const float4*)(gw + ch * 4));
        float4 wj = __ldg((const float4*)(gw + C1 + ch * 4));
        uint2* xt = (uint2*)g_x16;
#pragma unroll
        for (int s = 0; s < 8; s++) {
            int r = wid * 32 + s * 4 + rgrp;        // row = n*16 + b
            int n = r >> 4, b = r & 15;
            float4 v = *(const float4*)(X + ((size_t)b * Nn + n) * C1 + ch * 4);
            float vi = v.x * wi.x; vi = fmaf(v.y, wi.y, vi);
            vi = fmaf(v.z, wi.z, vi); vi = fmaf(v.w, wi.w, vi);
            float vj = v.x * wj.x; vj = fmaf(v.y, wj.y, vj);
            vj = fmaf(v.z, wj.z, vj); vj = fmaf(v.w, wj.w, vj);
#pragma unroll
            for (int off = 1; off < 8; off <<= 1) {
                vi += __shfl_xor_sync(0xffffffffu, vi, off);
                vj += __shfl_xor_sync(0xffffffffu, vj, off);
            }
            __half2 ha = __float22half2_rn(make_float2(v.x, v.y));
            __half2 hb = __float22half2_rn(make_float2(v.z, v.w));
            uint2 u;
            u.x = *(unsigned*)&ha; u.y = *(unsigned*)&hb;
            xt[r * 8 + ch] = u;
            if (ch == 0) {
                g_gi1[r]  = vi;
                g_gj1h[r] = __float2half_rn(vj);
            }
        }
    }
}

// ---------------- layer 1 fused: edge aggregation + combine ------------------
__global__ void __launch_bounds__(WPB * 32)
k_l1(const float* __restrict__ gw, const float* __restrict__ gb,
     const float* __restrict__ ampw, const float* __restrict__ w,
     const float* __restrict__ bias, const float* __restrict__ gw2) {
    __shared__ float smbuf[WPB][16][2 * C1];   // [b][x(32)|aggr(32)]
    int n = blockIdx.x * WPB + (threadIdx.x >> 5);
    if (n >= Nn) return;
    int lane = threadIdx.x & 31;
    int bq = lane >> 2;          // 0..7
    int cq = lane & 3;           // 0..3
    float (*sm)[2 * C1] = smbuf[threadIdx.x >> 5];

    float wge = __ldg(&gw[2 * C1]);
    float gbv = __ldg(gb);
    float givb = ((lane < 16) ? g_gi1[n * 16 + lane] : 0.f) + gbv;

    int cnt = g_cur1[n];
    if (lane == 0) g_cur1[n] = 0;        // reset for next replay (graph-safe)
    if (cnt > DMAX) cnt = DMAX;
    int beg = n * DMAX;
    int end = beg + cnt;

    const int off0 = bq * 4 + cq;
    const int off1 = 32 + bq * 4 + cq;

    float acc[16];
#pragma unroll
    for (int i = 0; i < 16; i++) acc[i] = 0.f;

    if (beg < end) {
        int2 mc = g_meta1[beg];
        int2 mn = (beg + 1 < end) ? g_meta1[beg + 1] : mc;
        float gjc = (lane < 16) ? __half2float(g_gj1h[mc.x * 16 + lane]) : 0.f;
        uint4 x0c = g_x16[(size_t)mc.x * 64 + off0];
        uint4 x1c = g_x16[(size_t)mc.x * 64 + off1];

#pragma unroll 2
        for (int k = beg; k < end; k++) {
            int2  mnn = (k + 2 < end) ? g_meta1[k + 2] : mn;
            float gjn = (lane < 16) ? __half2float(g_gj1h[mn.x * 16 + lane]) : 0.f;
            uint4 x0n = g_x16[(size_t)mn.x * 64 + off0];
            uint4 x1n = g_x16[(size_t)mn.x * 64 + off1];

            float ew = __int_as_float(mc.y);
            float z  = givb + gjc + ew * wge;
            float lamb = __fdividef(ew, 1.f + __expf(-z));   // lane = batch (lanes<16)
            float c0 = __shfl_sync(0xffffffffu, lamb, bq);
            float c1 = __shfl_sync(0xffffffffu, lamb, 8 + bq);

            const __half2* hp0 = (const __half2*)&x0c;
            const __half2* hp1 = (const __half2*)&x1c;
#pragma unroll
            for (int j = 0; j < 4; j++) {
                float2 f0 = __half22float2(hp0[j]);
                float2 f1 = __half22float2(hp1[j]);
                acc[2*j]     = fmaf(c0, f0.x, acc[2*j]);
                acc[2*j+1]   = fmaf(c0, f0.y, acc[2*j+1]);
                acc[8+2*j]   = fmaf(c1, f1.x, acc[8+2*j]);
                acc[8+2*j+1] = fmaf(c1, f1.y, acc[8+2*j+1]);
            }
            mc = mn; mn = mnn; gjc = gjn; x0c = x0n; x1c = x1n;
        }
    }

    float cntf = (float)cnt;
    if (cntf < 1.f) cntf = 1.f;
    float inv = __fdividef(1.f, cntf);
    float4 av0 = *(const float4*)(ampw + 8 * cq);
    float4 av1 = *(const float4*)(ampw + 8 * cq + 4);
    av0.x *= inv; av0.y *= inv; av0.z *= inv; av0.w *= inv;
    av1.x *= inv; av1.y *= inv; av1.z *= inv; av1.w *= inv;

    // stage aggr into smem [b][32 + c]
    *(float4*)&sm[bq][C1 + 8 * cq] =
        make_float4(acc[0]*av0.x, acc[1]*av0.y, acc[2]*av0.z, acc[3]*av0.w);
    *(float4*)&sm[bq][C1 + 8 * cq + 4] =
        make_float4(acc[4]*av1.x, acc[5]*av1.y, acc[6]*av1.z, acc[7]*av1.w);
    *(float4*)&sm[8 + bq][C1 + 8 * cq] =
        make_float4(acc[8]*av0.x, acc[9]*av0.y, acc[10]*av0.z, acc[11]*av0.w);
    *(float4*)&sm[8 + bq][C1 + 8 * cq + 4] =
        make_float4(acc[12]*av1.x, acc[13]*av1.y, acc[14]*av1.z, acc[15]*av1.w);

    // stage x_dst rows from g_x16 (fp16, contiguous, L2-hot)
#pragma unroll
    for (int hf = 0; hf < 2; hf++) {
        uint4 u = g_x16[(size_t)n * 64 + hf * 32 + lane];
        int b = (lane >> 2) + 8 * hf;
        int cg = lane & 3;
        const __half2* hp = (const __half2*)&u;
#pragma unroll
        for (int j = 0; j < 4; j++) {
            float2 f = __half22float2(hp[j]);
            sm[b][cg * 8 + 2*j]     = f.x;
            sm[b][cg * 8 + 2*j + 1] = f.y;
        }
    }
    __syncwarp();

    // combine: per batch, split-K (oc = lane&15, kh = lane>>4)
    int oc = lane & 15;
    int kh = lane >> 4;
    float wv[32];
#pragma unroll
    for (int kk = 0; kk < 32; kk++)
        wv[kk] = __ldg(&w[(kh * 32 + kk) * C2 + oc]);
    float bv   = __ldg(&bias[oc]);
    float gsel = __ldg(&gw2[lane]);     // lanes 0-15: wg_i[oc]; lanes 16-31: wg_j[oc]

    __half* hout = (__half*)g_h16;
#pragma unroll 4
    for (int b = 0; b < 16; b++) {
        float p0 = 0.f, p1 = 0.f;
#pragma unroll
        for (int kq = 0; kq < 8; kq += 2) {
            float4 m0 = *(float4*)&sm[b][kh * 32 + kq * 4];
            float4 m1 = *(float4*)&sm[b][kh * 32 + kq * 4 + 4];
            p0 = fmaf(m0.x, wv[kq*4+0], p0);
            p0 = fmaf(m0.y, wv[kq*4+1], p0);
            p0 = fmaf(m0.z, wv[kq*4+2], p0);
            p0 = fmaf(m0.w, wv[kq*4+3], p0);
            p1 = fmaf(m1.x, wv[kq*4+4], p1);
            p1 = fmaf(m1.y, wv[kq*4+5], p1);
            p1 = fmaf(m1.z, wv[kq*4+6], p1);
            p1 = fmaf(m1.w, wv[kq*4+7], p1);
        }
        float p = p0 + p1;
        p += __shfl_xor_sync(0xffffffffu, p, 16);
        float o = p + bv;
        o = (o > 0.f) ? o : 0.01f * o;

        // gate dots: lanes 0-15 reduce vi, lanes 16-31 reduce vj (same o per oc)
        float v = o * gsel;
#pragma unroll
        for (int off = 1; off < 16; off <<= 1)
            v += __shfl_xor_sync(0xffffffffu, v, off);

        if (lane < 16)
            hout[((size_t)n * 16 + b) * C2 + oc] = __float2half_rn(o);
        if (lane == 0)  g_gi2[n * 16 + b]  = v;
        if (lane == 16) g_gj2h[n * 16 + b] = __float2half_rn(v);
    }
}

// ---------------- layer 2 fused: edge aggregation + combine ------------------
__global__ void __launch_bounds__(WPB * 32)
k_l2(const float* __restrict__ gw, const float* __restrict__ gb,
     const float* __restrict__ ampw, const float* __restrict__ w,
     const float* __restrict__ bias, float* __restrict__ outp) {
    __shared__ float smbuf[WPB][16][2 * C2];   // [b][h(16)|aggr(16)]
    int n = blockIdx.x * WPB + (threadIdx.x >> 5);
    if (n >= Nn) return;
    int lane = threadIdx.x & 31;
    int bl = lane >> 1;          // 0..15
    int ch = lane & 1;           // 0..1
    float (*sm)[2 * C2] = smbuf[threadIdx.x >> 5];

    float wge = __ldg(&gw[2 * C2]);
    float gbv = __ldg(gb);
    float givb = ((lane < 16) ? g_gi2[n * 16 + lane] : 0.f) + gbv;

    int cnt = g_cur2[n];
    if (lane == 0) g_cur2[n] = 0;        // reset for next replay (graph-safe)
    if (cnt > DMAX) cnt = DMAX;
    int beg = n * DMAX;
    int end = beg + cnt;

    float acc[8];
#pragma unroll
    for (int i = 0; i < 8; i++) acc[i] = 0.f;

    if (beg < end) {
        int2 mc = g_meta2[beg];
        int2 mn = (beg + 1 < end) ? g_meta2[beg + 1] : mc;
        float gjc = (lane < 16) ? __half2float(g_gj2h[mc.x * 16 + lane]) : 0.f;
        uint4 xc = g_h16[(size_t)mc.x * 32 + lane];

#pragma unroll 2
        for (int k = beg; k < end; k++) {
            int2  mnn = (k + 2 < end) ? g_meta2[k + 2] : mn;
            float gjn = (lane < 16) ? __half2float(g_gj2h[mn.x * 16 + lane]) : 0.f;
            uint4 xn = g_h16[(size_t)mn.x * 32 + lane];

            float ew = __int_as_float(mc.y);
            float z  = givb + gjc + ew * wge;
            float lamb = __fdividef(ew, 1.f + __expf(-z));
            float c0 = __shfl_sync(0xffffffffu, lamb, bl);

            const __half2* hp = (const __half2*)&xc;
#pragma unroll
            for (int j = 0; j < 4; j++) {
                float2 f = __half22float2(hp[j]);
                acc[2*j]   = fmaf(c0, f.x, acc[2*j]);
                acc[2*j+1] = fmaf(c0, f.y, acc[2*j+1]);
            }
            mc = mn; mn = mnn; gjc = gjn; xc = xn;
        }
    }

    float cntf = (float)cnt;
    if (cntf < 1.f) cntf = 1.f;
    float inv = __fdividef(1.f, cntf);
    float4 av0 = *(const float4*)(ampw + 8 * ch);
    float4 av1 = *(const float4*)(ampw + 8 * ch + 4);
    av0.x *= inv; av0.y *= inv; av0.z *= inv; av0.w *= inv;
    av1.x *= inv; av1.y *= inv; av1.z *= inv; av1.w *= inv;

    // stage aggr into smem [b][16 + c]
    *(float4*)&sm[bl][C2 + 8 * ch] =
        make_float4(acc[0]*av0.x, acc[1]*av0.y, acc[2]*av0.z, acc[3]*av0.w);
    *(float4*)&sm[bl][C2 + 8 * ch + 4] =
        make_float4(acc[4]*av1.x, acc[5]*av1.y, acc[6]*av1.z, acc[7]*av1.w);

    // stage own h rows: one uint4 per lane (b = lane>>1, channels (lane&1)*8..)
    {
        uint4 u = g_h16[(size_t)n * 32 + lane];
        int b = lane >> 1;
        int off = (lane & 1) * 8;
        const __half2* hp = (const __half2*)&u;
#pragma unroll
        for (int j = 0; j < 4; j++) {
            float2 f = __half22float2(hp[j]);
            sm[b][off + 2*j]     = f.x;
            sm[b][off + 2*j + 1] = f.y;
        }
    }
    __syncwarp();

    // combine: per batch, oc = lane (32 outputs)
    float wv[32];
#pragma unroll
    for (int kk = 0; kk < 32; kk++)
        wv[kk] = __ldg(&w[kk * C3 + lane]);
    float bv = __ldg(&bias[lane]);

#pragma unroll 4
    for (int b = 0; b < 16; b++) {
        float p0 = bv, p1 = 0.f;
#pragma unroll
        for (int kq = 0; kq < 8; kq += 2) {
            float4 m0 = *(float4*)&sm[b][kq * 4];
            float4 m1 = *(float4*)&sm[b][kq * 4 + 4];
            p0 = fmaf(m0.x, wv[kq*4+0], p0);
            p0 = fmaf(m0.y, wv[kq*4+1], p0);
            p0 = fmaf(m0.z, wv[kq*4+2], p0);
            p0 = fmaf(m0.w, wv[kq*4+3], p0);
            p1 = fmaf(m1.x, wv[kq*4+4], p1);
            p1 = fmaf(m1.y, wv[kq*4+5], p1);
            p1 = fmaf(m1.z, wv[kq*4+6], p1);
            p1 = fmaf(m1.w, wv[kq*4+7], p1);
        }
        outp[((size_t)b * Nn + n) * C3 + lane] = p0 + p1;
    }
}

// ---------------- launch -----------------------------------------------------
extern "C" void kernel_launch(void* const* d_in, const int* in_sizes, int n_in,
                              void* d_out, int out_size) {
    const float* X       = (const float*)d_in[0];
    const int*   ei1     = (const int*)d_in[1];
    const float* ew1     = (const float*)d_in[2];
    const int*   ei2     = (const int*)d_in[4];
    const float* ew2     = (const float*)d_in[5];
    const float* amp_w1  = (const float*)d_in[7];
    const float* gate_w1 = (const float*)d_in[8];
    const float* gate_b1 = (const float*)d_in[9];
    const float* w1      = (const float*)d_in[10];
    const float* b1      = (const float*)d_in[11];
    const float* amp_w2  = (const float*)d_in[12];
    const float* gate_w2 = (const float*)d_in[13];
    const float* gate_b2 = (const float*)d_in[14];
    const float* w2      = (const float*)d_in[15];
    const float* b2      = (const float*)d_in[16];
    float* out = (float*)d_out;

    k_fill_prep<<<FB + PB, 256>>>(ei1, ew1, ei2, ew2, X, gate_w1);

    const int node_grid = (Nn + WPB - 1) / WPB;
    k_l1<<<node_grid, WPB * 32>>>(gate_w1, gate_b1, amp_w1, w1, b1, gate_w2);
    k_l2<<<node_grid, WPB * 32>>>(gate_w2, gate_b2, amp_w2, w2, b2, out);
}